// round 1
// baseline (speedup 1.0000x reference)
#include <cuda_runtime.h>
#include <mma.h>

using namespace nvcuda;

// Problem constants
#define BSZ  2048
#define TT   60
#define FF   89
#define HH   1024
#define G4H  4096
#define OUTN 30

// LSTM state (device globals; allocation-free scratch).
// h needs ping-pong: step t reads g_hbuf[t&1], writes g_hbuf[(t+1)&1].
// c is tile-exclusive per block -> safe in place.
__device__ float g_hbuf[2][(size_t)BSZ * HH];
__device__ float g_c[(size_t)BSZ * HH];

// Tiling
constexpr int BM  = 64;        // batch rows per block
constexpr int BH  = 64;        // h-columns per block (x4 gates = 256 z cols)
constexpr int KC  = 32;        // K chunk (4 wmma k-steps of 8)
constexpr int LDA = KC + 4;    // 36 (16B multiple)
constexpr int BNG = 256;       // 4 gate strips * 64
constexpr int LDB = BNG + 4;   // 260 (16B multiple)

__global__ void zero_state_kernel() {
    size_t n = (size_t)BSZ * HH;
    for (size_t i = (size_t)blockIdx.x * blockDim.x + threadIdx.x; i < n;
         i += (size_t)gridDim.x * blockDim.x) {
        g_hbuf[0][i] = 0.f;
        g_c[i] = 0.f;
    }
}

__device__ __forceinline__ float sigm(float x) { return 1.f / (1.f + __expf(-x)); }

// One LSTM timestep: z = x_t @ W + h @ U + b (bias folded in as synthetic K row),
// then gates i,f,g,o (Keras order), c/h update. Grid: (2048/64, 1024/64) = (32,16).
__global__ __launch_bounds__(256, 2)
void lstm_step_kernel(const float* __restrict__ x,
                      const float* __restrict__ W,
                      const float* __restrict__ U,
                      const float* __restrict__ bias,
                      int t)
{
    __shared__ float sA[BM][LDA];
    __shared__ float sB[KC][LDB];

    const float* __restrict__ hin  = g_hbuf[t & 1];
    float*       __restrict__ hout = g_hbuf[(t + 1) & 1];

    const int bm0 = blockIdx.x * BM;
    const int hc0 = blockIdx.y * BH;
    const int tid = threadIdx.x;
    const int wid = tid >> 5;
    const int warp_m = wid >> 2;   // 0..1  (32 rows each)
    const int warp_n = wid & 3;    // 0..3  (16 h-cols each)

    wmma::fragment<wmma::accumulator, 16, 16, 8, float> acc[2][4];
#pragma unroll
    for (int i = 0; i < 2; i++)
#pragma unroll
        for (int g = 0; g < 4; g++) wmma::fill_fragment(acc[i][g], 0.f);

    const int NCH_U = HH / KC;     // 32 chunks over U (K=1024)
    const int NCH   = NCH_U + 3;   // + 3 chunks over W region padded to 96 (89 + bias row + zeros)

    for (int ch = 0; ch < NCH; ++ch) {
        if (ch < NCH_U) {
            const int k0 = ch * KC;
            // A tile: h rows [bm0..bm0+63], k [k0..k0+31]  (512 float4)
#pragma unroll
            for (int i = 0; i < 2; i++) {
                int slot = tid + i * 256;
                int r = slot >> 3, q = slot & 7;
                float4 v = *reinterpret_cast<const float4*>(
                    &hin[(size_t)(bm0 + r) * HH + k0 + q * 4]);
                sA[r][q * 4 + 0] = wmma::__float_to_tf32(v.x);
                sA[r][q * 4 + 1] = wmma::__float_to_tf32(v.y);
                sA[r][q * 4 + 2] = wmma::__float_to_tf32(v.z);
                sA[r][q * 4 + 3] = wmma::__float_to_tf32(v.w);
            }
            // B tile: U rows [k0..k0+31], 4 gate strips of 64 cols  (2048 float4)
#pragma unroll
            for (int i = 0; i < 8; i++) {
                int slot = tid + i * 256;
                int k = slot >> 6, c4 = slot & 63;
                int col = c4 * 4;
                int strip = col >> 6, j = col & 63;
                int gcol = strip * HH + hc0 + j;
                float4 v = *reinterpret_cast<const float4*>(
                    &U[(size_t)(k0 + k) * G4H + gcol]);
                sB[k][col + 0] = wmma::__float_to_tf32(v.x);
                sB[k][col + 1] = wmma::__float_to_tf32(v.y);
                sB[k][col + 2] = wmma::__float_to_tf32(v.z);
                sB[k][col + 3] = wmma::__float_to_tf32(v.w);
            }
        } else {
            const int kw0 = (ch - NCH_U) * KC;
            // A tile from x_t (k<89), bias row (k==89), zeros beyond
            for (int idx = tid; idx < BM * KC; idx += 256) {
                int r = idx >> 5, kk = idx & 31;
                int kw = kw0 + kk;
                float v = 0.f;
                if (kw < FF)       v = x[(size_t)(bm0 + r) * (TT * FF) + t * FF + kw];
                else if (kw == FF) v = 1.f;
                sA[r][kk] = wmma::__float_to_tf32(v);
            }
            for (int idx = tid; idx < KC * BNG; idx += 256) {
                int k = idx >> 8, c = idx & 255;
                int strip = c >> 6, j = c & 63;
                int gcol = strip * HH + hc0 + j;
                int kw = kw0 + k;
                float v = 0.f;
                if (kw < FF)       v = W[(size_t)kw * G4H + gcol];
                else if (kw == FF) v = bias[gcol];
                sB[k][c] = wmma::__float_to_tf32(v);
            }
        }
        __syncthreads();

#pragma unroll
        for (int kk = 0; kk < 4; ++kk) {
            wmma::fragment<wmma::matrix_a, 16, 16, 8, wmma::precision::tf32,
                           wmma::row_major> afr0, afr1;
            wmma::load_matrix_sync(afr0, &sA[warp_m * 32][kk * 8], LDA);
            wmma::load_matrix_sync(afr1, &sA[warp_m * 32 + 16][kk * 8], LDA);
#pragma unroll
            for (int g = 0; g < 4; ++g) {
                wmma::fragment<wmma::matrix_b, 16, 16, 8, wmma::precision::tf32,
                               wmma::row_major> bfr;
                wmma::load_matrix_sync(bfr, &sB[kk * 8][g * 64 + warp_n * 16], LDB);
                wmma::mma_sync(acc[0][g], afr0, bfr, acc[0][g]);
                wmma::mma_sync(acc[1][g], afr1, bfr, acc[1][g]);
            }
        }
        __syncthreads();
    }

    // Epilogue: gates + state update entirely in registers.
    // Accumulator fragments of identical shape share per-thread layout, so
    // element e of (i,f,g,o,c_old) all refer to the same (row,col).
    const int col0 = hc0 + warp_n * 16;
#pragma unroll
    for (int mf = 0; mf < 2; ++mf) {
        const int row0 = bm0 + warp_m * 32 + mf * 16;
        wmma::fragment<wmma::accumulator, 16, 16, 8, float> cold;
        wmma::load_matrix_sync(cold, &g_c[(size_t)row0 * HH + col0], HH,
                               wmma::mem_row_major);
#pragma unroll
        for (int e = 0; e < cold.num_elements; ++e) {
            float iv = sigm(acc[mf][0].x[e]);
            float fv = sigm(acc[mf][1].x[e]);
            float gv = fmaxf(acc[mf][2].x[e], 0.f);   // activation='relu' on candidate
            float ov = sigm(acc[mf][3].x[e]);
            float cn = fv * cold.x[e] + iv * gv;
            acc[mf][0].x[e] = cn;                      // new c
            acc[mf][1].x[e] = ov * fmaxf(cn, 0.f);     // new h (relu on cell output)
        }
        wmma::store_matrix_sync(&g_c[(size_t)row0 * HH + col0], acc[mf][0], HH,
                                wmma::mem_row_major);
        wmma::store_matrix_sync(&hout[(size_t)row0 * HH + col0], acc[mf][1], HH,
                                wmma::mem_row_major);
    }
}

// Final dense head: y = h_T @ Wd + bd, out shape [B, 30, 1].
// After 60 steps the final h lives in g_hbuf[(59+1)&1] = g_hbuf[0].
__global__ void dense_kernel(const float* __restrict__ Wd,
                             const float* __restrict__ bd,
                             float* __restrict__ out)
{
    __shared__ float sh[HH];
    const int b = blockIdx.x;
    for (int i = threadIdx.x; i < HH; i += blockDim.x)
        sh[i] = g_hbuf[0][(size_t)b * HH + i];
    __syncthreads();
    if (threadIdx.x < OUTN) {
        const int o = threadIdx.x;
        float a = bd[o];
#pragma unroll 8
        for (int k = 0; k < HH; ++k) a += sh[k] * Wd[k * OUTN + o];
        out[(size_t)b * OUTN + o] = a;
    }
}

extern "C" void kernel_launch(void* const* d_in, const int* in_sizes, int n_in,
                              void* d_out, int out_size)
{
    (void)in_sizes; (void)n_in; (void)out_size;
    const float* x  = (const float*)d_in[0];
    const float* W  = (const float*)d_in[1];
    const float* U  = (const float*)d_in[2];
    const float* b  = (const float*)d_in[3];
    const float* Wd = (const float*)d_in[4];
    const float* bd = (const float*)d_in[5];
    float* out = (float*)d_out;

    zero_state_kernel<<<1024, 256>>>();

    dim3 grid(BSZ / BM, HH / BH);  // (32, 16)
    for (int t = 0; t < TT; ++t) {
        lstm_step_kernel<<<grid, 256>>>(x, W, U, b, t);
    }

    dense_kernel<<<BSZ, 128>>>(Wd, bd, out);
}

// round 3
// speedup vs baseline: 2.8574x; 2.8574x over previous
#include <cuda_runtime.h>
#include <cstdint>

// Problem constants
#define BSZ  2048
#define TT   60
#define FF   89
#define HH   1024
#define G4H  4096
#define OUTN 30
#define KTOT 1152          // 1024 (U) + 89 (W) + 1 (bias) + 38 pad
#define NCHK 36            // KTOT / 32

// Device-global scratch (allocation-free).
__device__ float g_hbuf[2][(size_t)BSZ * HH];
__device__ float g_c[(size_t)BSZ * HH];
__device__ float g_B[(size_t)G4H * KTOT];          // B[n][k] K-major, tf32-rounded
__device__ float g_Ax[(size_t)TT * BSZ * 128];     // packed [x_t | 1 | 0pad] per step

// ---------------- helpers ----------------
__device__ __forceinline__ uint32_t smem_u32(const void* p) {
    uint32_t a;
    asm("{ .reg .u64 t; cvta.to.shared.u64 t, %1; cvt.u32.u64 %0, t; }"
        : "=r"(a) : "l"(p));
    return a;
}
__device__ __forceinline__ float rtf32(float v) {
    unsigned r; asm("cvt.rna.tf32.f32 %0, %1;" : "=r"(r) : "f"(v));
    return __uint_as_float(r);
}
__device__ __forceinline__ void cp16(uint32_t dst, const float* src) {
    asm volatile("cp.async.cg.shared.global [%0], [%1], 16;" :: "r"(dst), "l"(src));
}
__device__ __forceinline__ void ldm_x4(uint32_t a, uint32_t& r0, uint32_t& r1,
                                       uint32_t& r2, uint32_t& r3) {
    asm volatile("ldmatrix.sync.aligned.m8n8.x4.shared.b16 {%0,%1,%2,%3}, [%4];"
                 : "=r"(r0), "=r"(r1), "=r"(r2), "=r"(r3) : "r"(a));
}
__device__ __forceinline__ void mma_tf32(float& d0, float& d1, float& d2, float& d3,
                                         uint32_t a0, uint32_t a1, uint32_t a2,
                                         uint32_t a3, uint32_t b0, uint32_t b1) {
    asm volatile(
        "mma.sync.aligned.m16n8k8.row.col.f32.tf32.tf32.f32 "
        "{%0,%1,%2,%3}, {%4,%5,%6,%7}, {%8,%9}, {%0,%1,%2,%3};"
        : "+f"(d0), "+f"(d1), "+f"(d2), "+f"(d3)
        : "r"(a0), "r"(a1), "r"(a2), "r"(a3), "r"(b0), "r"(b1));
}

// ---------------- prologue kernels ----------------
__global__ void zero_state_kernel() {
    size_t n = (size_t)BSZ * HH;
    for (size_t i = (size_t)blockIdx.x * blockDim.x + threadIdx.x; i < n;
         i += (size_t)gridDim.x * blockDim.x) {
        g_hbuf[0][i] = 0.f;
        g_c[i] = 0.f;
    }
}

// B[n][k]: k<1024 -> U[k][n]; k<1113 -> W[k-1024][n]; k==1113 -> bias[n]; else 0
__global__ void pack_B_kernel(const float* __restrict__ W,
                              const float* __restrict__ U,
                              const float* __restrict__ bias) {
    size_t total = (size_t)G4H * KTOT;
    for (size_t idx = (size_t)blockIdx.x * blockDim.x + threadIdx.x; idx < total;
         idx += (size_t)gridDim.x * blockDim.x) {
        int n = (int)(idx / KTOT);
        int k = (int)(idx % KTOT);
        float v = 0.f;
        if (k < HH)            v = U[(size_t)k * G4H + n];
        else if (k < HH + FF)  v = W[(size_t)(k - HH) * G4H + n];
        else if (k == HH + FF) v = bias[n];
        g_B[idx] = rtf32(v);
    }
}

// Ax[t][m][j]: j<89 -> x[m][t][j]; j==89 -> 1; else 0
__global__ void pack_Ax_kernel(const float* __restrict__ x) {
    size_t total = (size_t)TT * BSZ * 128;
    for (size_t idx = (size_t)blockIdx.x * blockDim.x + threadIdx.x; idx < total;
         idx += (size_t)gridDim.x * blockDim.x) {
        int j  = (int)(idx & 127);
        int tm = (int)(idx >> 7);
        int m  = tm & (BSZ - 1);
        int t  = tm >> 11;
        float v = 0.f;
        if (j < FF)       v = x[(size_t)m * (TT * FF) + t * FF + j];
        else if (j == FF) v = 1.f;
        g_Ax[idx] = rtf32(v);
    }
}

// ---------------- main step kernel (mma.sync tf32 + ldmatrix) ----------------
// CTA tile: M=128 rows x 128 z-cols (= 32 h-cols x 4 gates). 256 threads, 8 warps,
// each warp 64x32 (4 m-frags x 4 n-frags; n-frag g = gate g of the warp's 8 h-cols).
// Grid (16, 32). 3-stage cp.async pipeline, 32 KB/stage.
#define STAGE_BYTES 32768
#define SMEM_DYN (3 * STAGE_BYTES)

__global__ __launch_bounds__(256, 2) void lstm_step_tc(int t) {
    extern __shared__ char dsm[];
    const uint32_t smem0 = smem_u32(dsm);
    const int tid  = threadIdx.x;
    const int lane = tid & 31;
    const int wid  = tid >> 5;
    const int wm   = wid >> 2;           // 0..1 : 64-row half
    const int wn   = wid & 3;            // 0..3 : 8-h-col group

    const float* __restrict__ hin  = g_hbuf[t & 1];
    float*       __restrict__ hout = g_hbuf[(t + 1) & 1];
    const int m0  = blockIdx.x * 128;
    const int hc0 = blockIdx.y * 32;

    // Global row index for each B smem row n_s (0..127):
    //   wg = n_s>>5 (warp group), g = (n_s>>3)&3 (gate), j8 = n_s&7
    //   n = g*1024 + hc0 + wg*8 + j8
    // Loader: thread handles rows idx>>3, segs idx&7 (idx = tid + j*256).
    auto load_chunk = [&](int c, int s) {
        const uint32_t aBase = smem0 + s * STAGE_BYTES;
        const uint32_t bBase = aBase + 16384;
        const int k0 = c * 32;
#pragma unroll
        for (int j = 0; j < 4; j++) {
            int idx = tid + j * 256;
            int row = idx >> 3, seg = idx & 7;
            const float* src;
            if (k0 < HH)
                src = hin + (size_t)(m0 + row) * HH + k0 + seg * 4;
            else
                src = g_Ax + ((size_t)t * BSZ + m0 + row) * 128 + (k0 - HH) + seg * 4;
            cp16(aBase + row * 128 + ((seg ^ (row & 7)) << 4), src);
        }
#pragma unroll
        for (int j = 0; j < 4; j++) {
            int idx = tid + j * 256;
            int row = idx >> 3, seg = idx & 7;
            int n = (((row >> 3) & 3) << 10) + hc0 + ((row >> 5) << 3) + (row & 7);
            cp16(bBase + row * 128 + ((seg ^ (row & 7)) << 4),
                 g_B + (size_t)n * KTOT + k0 + seg * 4);
        }
        asm volatile("cp.async.commit_group;" ::: "memory");
    };

    float acc[4][4][4];   // [mfrag][gate][elem]
#pragma unroll
    for (int mf = 0; mf < 4; mf++)
#pragma unroll
        for (int g = 0; g < 4; g++)
#pragma unroll
            for (int e = 0; e < 4; e++) acc[mf][g][e] = 0.f;

    load_chunk(0, 0);
    load_chunk(1, 1);

    // ldmatrix lane addressing (precomputed per-thread row/seg components):
    // A: row = wm*64 + mf*16 + (lane&15), seg = 2*ks + (lane>>4)
    const int aRow = wm * 64 + (lane & 15);
    const int aSegL = lane >> 4;
    // B: row = wn*32 + pair*16 + ((lane>>4)<<3) + (lane&7), seg = 2*ks + ((lane>>3)&1)
    const int bRow = wn * 32 + ((lane >> 4) << 3) + (lane & 7);
    const int bSegL = (lane >> 3) & 1;

    for (int ch = 0; ch < NCHK; ++ch) {
        int cl = ch + 2;
        if (cl < NCHK) load_chunk(cl, cl % 3);
        else asm volatile("cp.async.commit_group;" ::: "memory");

        asm volatile("cp.async.wait_group 2;" ::: "memory");
        __syncthreads();

        const uint32_t aBase = smem0 + (ch % 3) * STAGE_BYTES;
        const uint32_t bBase = aBase + 16384;
#pragma unroll
        for (int ks = 0; ks < 4; ++ks) {
            uint32_t b[2][4];
#pragma unroll
            for (int pr = 0; pr < 2; ++pr) {
                int row = bRow + pr * 16;
                int seg = 2 * ks + bSegL;
                ldm_x4(bBase + row * 128 + ((seg ^ (row & 7)) << 4),
                       b[pr][0], b[pr][1], b[pr][2], b[pr][3]);
            }
#pragma unroll
            for (int mf = 0; mf < 4; ++mf) {
                int row = aRow + mf * 16;
                int seg = 2 * ks + aSegL;
                uint32_t a0, a1, a2, a3;
                ldm_x4(aBase + row * 128 + ((seg ^ (row & 7)) << 4), a0, a1, a2, a3);
                mma_tf32(acc[mf][0][0], acc[mf][0][1], acc[mf][0][2], acc[mf][0][3],
                         a0, a1, a2, a3, b[0][0], b[0][1]);
                mma_tf32(acc[mf][1][0], acc[mf][1][1], acc[mf][1][2], acc[mf][1][3],
                         a0, a1, a2, a3, b[0][2], b[0][3]);
                mma_tf32(acc[mf][2][0], acc[mf][2][1], acc[mf][2][2], acc[mf][2][3],
                         a0, a1, a2, a3, b[1][0], b[1][1]);
                mma_tf32(acc[mf][3][0], acc[mf][3][1], acc[mf][3][2], acc[mf][3][3],
                         a0, a1, a2, a3, b[1][2], b[1][3]);
            }
        }
        __syncthreads();
    }

    // Epilogue: gates + state update entirely in registers.
    // Acc element map (m16n8): e0=(r0,cp), e1=(r0,cp+1), e2=(r0+8,cp), e3=(r0+8,cp+1)
    // where r0 = m0 + wm*64 + mf*16 + (lane>>2), cp = 2*(lane&3).
    {
        const int colg = hc0 + wn * 8 + 2 * (lane & 3);
#pragma unroll
        for (int mf = 0; mf < 4; ++mf) {
            const int r0 = m0 + wm * 64 + mf * 16 + (lane >> 2);
#pragma unroll
            for (int half = 0; half < 2; ++half) {
                const int r = r0 + half * 8;
                float2* cp2 = reinterpret_cast<float2*>(&g_c[(size_t)r * HH + colg]);
                float2* hp2 = reinterpret_cast<float2*>(&hout[(size_t)r * HH + colg]);
                float2 co = *cp2;
                float cold[2] = {co.x, co.y};
                float cn[2], hn[2];
#pragma unroll
                for (int q = 0; q < 2; ++q) {
                    int e = half * 2 + q;
                    float iv = 1.f / (1.f + __expf(-acc[mf][0][e]));
                    float fv = 1.f / (1.f + __expf(-acc[mf][1][e]));
                    float gv = fmaxf(acc[mf][2][e], 0.f);
                    float ov = 1.f / (1.f + __expf(-acc[mf][3][e]));
                    float c2 = fv * cold[q] + iv * gv;
                    cn[q] = c2;
                    hn[q] = rtf32(ov * fmaxf(c2, 0.f));  // tf32-round for next MMA
                }
                *cp2 = make_float2(cn[0], cn[1]);
                *hp2 = make_float2(hn[0], hn[1]);
            }
        }
    }
}

// ---------------- dense head ----------------
__global__ void dense_kernel(const float* __restrict__ Wd,
                             const float* __restrict__ bd,
                             float* __restrict__ out)
{
    __shared__ float red[8][32];
    const int b = blockIdx.x;
    const int tid = threadIdx.x;
    const int o = tid & 31;
    const int sg = tid >> 5;           // 8 k-segments of 128
    const float* __restrict__ h = &g_hbuf[0][(size_t)b * HH];
    float s = 0.f;
    if (o < OUTN) {
        const int k0 = sg * 128;
#pragma unroll 4
        for (int k = k0; k < k0 + 128; ++k) s += h[k] * Wd[k * OUTN + o];
    }
    red[sg][o] = s;
    __syncthreads();
    if (tid < OUTN) {
        float a = bd[tid];
#pragma unroll
        for (int i = 0; i < 8; ++i) a += red[i][tid];
        out[(size_t)b * OUTN + tid] = a;
    }
}

extern "C" void kernel_launch(void* const* d_in, const int* in_sizes, int n_in,
                              void* d_out, int out_size)
{
    (void)in_sizes; (void)n_in; (void)out_size;
    const float* x  = (const float*)d_in[0];
    const float* W  = (const float*)d_in[1];
    const float* U  = (const float*)d_in[2];
    const float* b  = (const float*)d_in[3];
    const float* Wd = (const float*)d_in[4];
    const float* bd = (const float*)d_in[5];
    float* out = (float*)d_out;

    cudaFuncSetAttribute(lstm_step_tc, cudaFuncAttributeMaxDynamicSharedMemorySize,
                         SMEM_DYN);

    zero_state_kernel<<<512, 256>>>();
    pack_B_kernel<<<2048, 256>>>(W, U, b);
    pack_Ax_kernel<<<4096, 256>>>(x);

    dim3 grid(BSZ / 128, HH / 32);   // (16, 32) = 512 CTAs
    for (int t = 0; t < TT; ++t) {
        lstm_step_tc<<<grid, 256, SMEM_DYN>>>(t);
    }

    dense_kernel<<<BSZ, 256>>>(Wd, bd, out);
}

// round 5
// speedup vs baseline: 3.3360x; 1.1675x over previous
#include <cuda_runtime.h>
#include <cstdint>

// Problem constants
#define BSZ  2048
#define TT   60
#define FF   89
#define HH   1024
#define G4H  4096
#define OUTN 30
#define KTOT 1152          // 1024 (U) + 89 (W) + 1 (bias) + 38 pad
#define NCHK 36            // KTOT / 32
#define NRB  16            // row blocks (2048/128)
#define NHB  32            // h-col blocks (1024/32)
#define NTILES 512         // NRB * NHB
#define NCTAS 296          // 148 SMs * 2 resident CTAs

// Device-global scratch (allocation-free).
__device__ float g_hbuf[2][(size_t)BSZ * HH];
__device__ float g_c[(size_t)BSZ * HH];
__device__ float g_B[(size_t)G4H * KTOT];          // B[n][k] K-major, tf32-rounded
__device__ float g_Ax[(size_t)TT * BSZ * 128];     // packed [x_t | 1 | 0pad] per step
__device__ int   g_cnt[TT][NRB];                   // per-(step,rowblock) done counters

// ---------------- helpers ----------------
__device__ __forceinline__ uint32_t smem_u32(const void* p) {
    uint32_t a;
    asm("{ .reg .u64 t; cvta.to.shared.u64 t, %1; cvt.u32.u64 %0, t; }"
        : "=r"(a) : "l"(p));
    return a;
}
__device__ __forceinline__ float rtf32(float v) {
    unsigned r; asm("cvt.rna.tf32.f32 %0, %1;" : "=r"(r) : "f"(v));
    return __uint_as_float(r);
}
__device__ __forceinline__ void cp16(uint32_t dst, const float* src) {
    asm volatile("cp.async.cg.shared.global [%0], [%1], 16;" :: "r"(dst), "l"(src));
}
__device__ __forceinline__ void ldm_x4(uint32_t a, uint32_t& r0, uint32_t& r1,
                                       uint32_t& r2, uint32_t& r3) {
    asm volatile("ldmatrix.sync.aligned.m8n8.x4.shared.b16 {%0,%1,%2,%3}, [%4];"
                 : "=r"(r0), "=r"(r1), "=r"(r2), "=r"(r3) : "r"(a));
}
__device__ __forceinline__ void mma_tf32(float& d0, float& d1, float& d2, float& d3,
                                         uint32_t a0, uint32_t a1, uint32_t a2,
                                         uint32_t a3, uint32_t b0, uint32_t b1) {
    asm volatile(
        "mma.sync.aligned.m16n8k8.row.col.f32.tf32.tf32.f32 "
        "{%0,%1,%2,%3}, {%4,%5,%6,%7}, {%8,%9}, {%0,%1,%2,%3};"
        : "+f"(d0), "+f"(d1), "+f"(d2), "+f"(d3)
        : "r"(a0), "r"(a1), "r"(a2), "r"(a3), "r"(b0), "r"(b1));
}

// ---------------- prologue kernels ----------------
__global__ void zero_state_kernel() {
    size_t n = (size_t)BSZ * HH;
    for (size_t i = (size_t)blockIdx.x * blockDim.x + threadIdx.x; i < n;
         i += (size_t)gridDim.x * blockDim.x) {
        g_hbuf[0][i] = 0.f;
        g_c[i] = 0.f;
    }
    // FIX: TT*NRB = 960 counters; must reset ALL of them every call
    // (graph replays reuse device globals — stale counters broke replay runs).
    for (int i = (int)(blockIdx.x * blockDim.x + threadIdx.x); i < TT * NRB;
         i += (int)(gridDim.x * blockDim.x))
        (&g_cnt[0][0])[i] = 0;
}

// B[n][k]: k<1024 -> U[k][n]; k<1113 -> W[k-1024][n]; k==1113 -> bias[n]; else 0
__global__ void pack_B_kernel(const float* __restrict__ W,
                              const float* __restrict__ U,
                              const float* __restrict__ bias) {
    size_t total = (size_t)G4H * KTOT;
    for (size_t idx = (size_t)blockIdx.x * blockDim.x + threadIdx.x; idx < total;
         idx += (size_t)gridDim.x * blockDim.x) {
        int n = (int)(idx / KTOT);
        int k = (int)(idx % KTOT);
        float v = 0.f;
        if (k < HH)            v = U[(size_t)k * G4H + n];
        else if (k < HH + FF)  v = W[(size_t)(k - HH) * G4H + n];
        else if (k == HH + FF) v = bias[n];
        g_B[idx] = rtf32(v);
    }
}

// Ax[t][m][j]: j<89 -> x[m][t][j]; j==89 -> 1; else 0
__global__ void pack_Ax_kernel(const float* __restrict__ x) {
    size_t total = (size_t)TT * BSZ * 128;
    for (size_t idx = (size_t)blockIdx.x * blockDim.x + threadIdx.x; idx < total;
         idx += (size_t)gridDim.x * blockDim.x) {
        int j  = (int)(idx & 127);
        int tm = (int)(idx >> 7);
        int m  = tm & (BSZ - 1);
        int t  = tm >> 11;
        float v = 0.f;
        if (j < FF)       v = x[(size_t)m * (TT * FF) + t * FF + j];
        else if (j == FF) v = 1.f;
        g_Ax[idx] = rtf32(v);
    }
}

// ---------------- persistent LSTM kernel ----------------
// 296 CTAs, each loops over (t, tile) items, t-major, stride NCTAS.
// CTA tile: 128 rows x 128 z-cols (32 h-cols x 4 gates). 8 warps, warp 64x32.
// Cross-step dependency via g_cnt[t][bx] counters (32 producers each).
#define STAGE_BYTES 32768
#define SMEM_DYN (3 * STAGE_BYTES)

__global__ __launch_bounds__(256, 2) void lstm_persistent() {
    extern __shared__ char dsm[];
    const uint32_t smem0 = smem_u32(dsm);
    const int tid  = threadIdx.x;
    const int lane = tid & 31;
    const int wid  = tid >> 5;
    const int wm   = wid >> 2;           // 0..1 : 64-row half
    const int wn   = wid & 3;            // 0..3 : 8-h-col group

    // ldmatrix lane addressing
    const int aRowL = wm * 64 + (lane & 15);
    const int aSegL = lane >> 4;
    const int bRowL = wn * 32 + ((lane >> 4) << 3) + (lane & 7);
    const int bSegL = (lane >> 3) & 1;

    const int NITEMS = TT * NTILES;
    for (int it = blockIdx.x; it < NITEMS; it += NCTAS) {
        const int t    = it >> 9;            // / 512
        const int tile = it & (NTILES - 1);
        const int bx   = tile >> 5;          // rowblock 0..15
        const int by   = tile & 31;          // h block 0..31
        const int m0   = bx * 128;
        const int hc0  = by * 32;

        const float* __restrict__ hin  = g_hbuf[t & 1];
        float*       __restrict__ hout = g_hbuf[(t + 1) & 1];

        // Wait for step t-1 rowblock bx to be fully produced.
        if (t > 0) {
            if (tid == 0) {
                const int* p = &g_cnt[t - 1][bx];
                int v;
                while (true) {
                    asm volatile("ld.acquire.gpu.global.b32 %0, [%1];"
                                 : "=r"(v) : "l"(p) : "memory");
                    if (v >= NHB) break;
                    __nanosleep(64);
                }
            }
            __syncthreads();
        }

        auto load_chunk = [&](int c, int s) {
            const uint32_t aBase = smem0 + s * STAGE_BYTES;
            const uint32_t bBase = aBase + 16384;
            const int k0 = c * 32;
#pragma unroll
            for (int j = 0; j < 4; j++) {
                int idx = tid + j * 256;
                int row = idx >> 3, seg = idx & 7;
                const float* src;
                if (k0 < HH)
                    src = hin + (size_t)(m0 + row) * HH + k0 + seg * 4;
                else
                    src = g_Ax + ((size_t)t * BSZ + m0 + row) * 128 + (k0 - HH) + seg * 4;
                cp16(aBase + row * 128 + ((seg ^ (row & 7)) << 4), src);
            }
#pragma unroll
            for (int j = 0; j < 4; j++) {
                int idx = tid + j * 256;
                int row = idx >> 3, seg = idx & 7;
                int n = (((row >> 3) & 3) << 10) + hc0 + ((row >> 5) << 3) + (row & 7);
                cp16(bBase + row * 128 + ((seg ^ (row & 7)) << 4),
                     g_B + (size_t)n * KTOT + k0 + seg * 4);
            }
            asm volatile("cp.async.commit_group;" ::: "memory");
        };

        float acc[4][4][4];   // [mfrag][gate][elem]
#pragma unroll
        for (int mf = 0; mf < 4; mf++)
#pragma unroll
            for (int g = 0; g < 4; g++)
#pragma unroll
                for (int e = 0; e < 4; e++) acc[mf][g][e] = 0.f;

        load_chunk(0, 0);
        load_chunk(1, 1);

        for (int ch = 0; ch < NCHK; ++ch) {
            int cl = ch + 2;
            if (cl < NCHK) load_chunk(cl, cl % 3);
            else asm volatile("cp.async.commit_group;" ::: "memory");

            asm volatile("cp.async.wait_group 2;" ::: "memory");
            __syncthreads();

            const uint32_t aBase = smem0 + (ch % 3) * STAGE_BYTES;
            const uint32_t bBase = aBase + 16384;
#pragma unroll
            for (int ks = 0; ks < 4; ++ks) {
                uint32_t b[2][4];
#pragma unroll
                for (int pr = 0; pr < 2; ++pr) {
                    int row = bRowL + pr * 16;
                    int seg = 2 * ks + bSegL;
                    ldm_x4(bBase + row * 128 + ((seg ^ (row & 7)) << 4),
                           b[pr][0], b[pr][1], b[pr][2], b[pr][3]);
                }
#pragma unroll
                for (int mf = 0; mf < 4; ++mf) {
                    int row = aRowL + mf * 16;
                    int seg = 2 * ks + aSegL;
                    uint32_t a0, a1, a2, a3;
                    ldm_x4(aBase + row * 128 + ((seg ^ (row & 7)) << 4),
                           a0, a1, a2, a3);
                    mma_tf32(acc[mf][0][0], acc[mf][0][1], acc[mf][0][2], acc[mf][0][3],
                             a0, a1, a2, a3, b[0][0], b[0][1]);
                    mma_tf32(acc[mf][1][0], acc[mf][1][1], acc[mf][1][2], acc[mf][1][3],
                             a0, a1, a2, a3, b[0][2], b[0][3]);
                    mma_tf32(acc[mf][2][0], acc[mf][2][1], acc[mf][2][2], acc[mf][2][3],
                             a0, a1, a2, a3, b[1][0], b[1][1]);
                    mma_tf32(acc[mf][3][0], acc[mf][3][1], acc[mf][3][2], acc[mf][3][3],
                             a0, a1, a2, a3, b[1][2], b[1][3]);
                }
            }
            __syncthreads();
        }

        // Epilogue: gates + state update in registers.
        {
            const int colg = hc0 + wn * 8 + 2 * (lane & 3);
#pragma unroll
            for (int mf = 0; mf < 4; ++mf) {
                const int r0 = m0 + wm * 64 + mf * 16 + (lane >> 2);
#pragma unroll
                for (int half = 0; half < 2; ++half) {
                    const int r = r0 + half * 8;
                    float2* cp2 = reinterpret_cast<float2*>(&g_c[(size_t)r * HH + colg]);
                    float2* hp2 = reinterpret_cast<float2*>(&hout[(size_t)r * HH + colg]);
                    float2 co = *cp2;
                    float cold[2] = {co.x, co.y};
                    float cn[2], hn[2];
#pragma unroll
                    for (int q = 0; q < 2; ++q) {
                        int e = half * 2 + q;
                        float iv = 1.f / (1.f + __expf(-acc[mf][0][e]));
                        float fv = 1.f / (1.f + __expf(-acc[mf][1][e]));
                        float gv = fmaxf(acc[mf][2][e], 0.f);
                        float ov = 1.f / (1.f + __expf(-acc[mf][3][e]));
                        float c2 = fv * cold[q] + iv * gv;
                        cn[q] = c2;
                        hn[q] = rtf32(ov * fmaxf(c2, 0.f));  // tf32-round for next MMA
                    }
                    *cp2 = make_float2(cn[0], cn[1]);
                    *hp2 = make_float2(hn[0], hn[1]);
                }
            }
        }

        // Publish: this tile's h rows/cols for step t are done.
        __threadfence();
        __syncthreads();
        if (tid == 0) atomicAdd(&g_cnt[t][bx], 1);
    }
}

// ---------------- dense head ----------------
__global__ void dense_kernel(const float* __restrict__ Wd,
                             const float* __restrict__ bd,
                             float* __restrict__ out)
{
    __shared__ float red[8][32];
    const int b = blockIdx.x;
    const int tid = threadIdx.x;
    const int o = tid & 31;
    const int sg = tid >> 5;           // 8 k-segments of 128
    const float* __restrict__ h = &g_hbuf[0][(size_t)b * HH];
    float s = 0.f;
    if (o < OUTN) {
        const int k0 = sg * 128;
#pragma unroll 4
        for (int k = k0; k < k0 + 128; ++k) s += h[k] * Wd[k * OUTN + o];
    }
    red[sg][o] = s;
    __syncthreads();
    if (tid < OUTN) {
        float a = bd[tid];
#pragma unroll
        for (int i = 0; i < 8; ++i) a += red[i][tid];
        out[(size_t)b * OUTN + tid] = a;
    }
}

extern "C" void kernel_launch(void* const* d_in, const int* in_sizes, int n_in,
                              void* d_out, int out_size)
{
    (void)in_sizes; (void)n_in; (void)out_size;
    const float* x  = (const float*)d_in[0];
    const float* W  = (const float*)d_in[1];
    const float* U  = (const float*)d_in[2];
    const float* b  = (const float*)d_in[3];
    const float* Wd = (const float*)d_in[4];
    const float* bd = (const float*)d_in[5];
    float* out = (float*)d_out;

    cudaFuncSetAttribute(lstm_persistent, cudaFuncAttributeMaxDynamicSharedMemorySize,
                         SMEM_DYN);

    zero_state_kernel<<<512, 256>>>();
    pack_B_kernel<<<2048, 256>>>(W, U, b);
    pack_Ax_kernel<<<4096, 256>>>(x);

    lstm_persistent<<<NCTAS, 256, SMEM_DYN>>>();

    dense_kernel<<<BSZ, 256>>>(Wd, bd, out);
}

// round 8
// speedup vs baseline: 3.5700x; 1.0702x over previous
#include <cuda_runtime.h>
#include <cstdint>

// Problem constants
#define BSZ  2048
#define TT   60
#define FF   89
#define HH   1024
#define G4H  4096
#define OUTN 30
// K layout (reordered): k 0..88 = W rows, k 89 = bias, k 90..95 = 0 pad,
// k 96..1119 = U rows. Total KTOT = 1120 = 35 chunks of 32.
#define KXP  96            // x-part width (W + bias + pad)
#define KTOT 1120
#define NCHK 35
#define NRB  16            // row blocks (2048/128)
#define NHB  32            // h-col blocks (1024/32)
#define NTILES 512         // NRB * NHB
#define NCTAS 296          // 148 SMs * 2 resident CTAs

// Device-global scratch (allocation-free).
__device__ float g_hbuf[2][(size_t)BSZ * HH];
__device__ float g_c[(size_t)BSZ * HH];
__device__ float g_B[(size_t)G4H * KTOT];          // B[n][k] K-major, tf32-rounded
__device__ float g_Ax[(size_t)TT * BSZ * 128];     // packed [x_t | 1 | 0pad] per step
__device__ int   g_cnt[TT][NRB];                   // per-(step,rowblock) done counters

// ---------------- helpers ----------------
__device__ __forceinline__ uint32_t smem_u32(const void* p) {
    uint32_t a;
    asm("{ .reg .u64 t; cvta.to.shared.u64 t, %1; cvt.u32.u64 %0, t; }"
        : "=r"(a) : "l"(p));
    return a;
}
__device__ __forceinline__ float rtf32(float v) {
    unsigned r; asm("cvt.rna.tf32.f32 %0, %1;" : "=r"(r) : "f"(v));
    return __uint_as_float(r);
}
__device__ __forceinline__ void cp16(uint32_t dst, const float* src) {
    asm volatile("cp.async.cg.shared.global [%0], [%1], 16;" :: "r"(dst), "l"(src));
}
__device__ __forceinline__ void ldm_x4(uint32_t a, uint32_t& r0, uint32_t& r1,
                                       uint32_t& r2, uint32_t& r3) {
    asm volatile("ldmatrix.sync.aligned.m8n8.x4.shared.b16 {%0,%1,%2,%3}, [%4];"
                 : "=r"(r0), "=r"(r1), "=r"(r2), "=r"(r3) : "r"(a));
}
__device__ __forceinline__ void mma_tf32(float& d0, float& d1, float& d2, float& d3,
                                         uint32_t a0, uint32_t a1, uint32_t a2,
                                         uint32_t a3, uint32_t b0, uint32_t b1) {
    asm volatile(
        "mma.sync.aligned.m16n8k8.row.col.f32.tf32.tf32.f32 "
        "{%0,%1,%2,%3}, {%4,%5,%6,%7}, {%8,%9}, {%0,%1,%2,%3};"
        : "+f"(d0), "+f"(d1), "+f"(d2), "+f"(d3)
        : "r"(a0), "r"(a1), "r"(a2), "r"(a3), "r"(b0), "r"(b1));
}

// ---------------- prologue kernels ----------------
__global__ void zero_state_kernel() {
    size_t n = (size_t)BSZ * HH;
    for (size_t i = (size_t)blockIdx.x * blockDim.x + threadIdx.x; i < n;
         i += (size_t)gridDim.x * blockDim.x) {
        g_hbuf[0][i] = 0.f;
        g_c[i] = 0.f;
    }
    // All TT*NRB counters must be reset every call (graph replays reuse globals).
    for (int i = (int)(blockIdx.x * blockDim.x + threadIdx.x); i < TT * NRB;
         i += (int)(gridDim.x * blockDim.x))
        (&g_cnt[0][0])[i] = 0;
}

// B[n][k]: k<89 -> W[k][n]; k==89 -> bias[n]; k<96 -> 0; else U[k-96][n]
__global__ void pack_B_kernel(const float* __restrict__ W,
                              const float* __restrict__ U,
                              const float* __restrict__ bias) {
    size_t total = (size_t)G4H * KTOT;
    for (size_t idx = (size_t)blockIdx.x * blockDim.x + threadIdx.x; idx < total;
         idx += (size_t)gridDim.x * blockDim.x) {
        int n = (int)(idx / KTOT);
        int k = (int)(idx % KTOT);
        float v = 0.f;
        if (k < FF)       v = W[(size_t)k * G4H + n];
        else if (k == FF) v = bias[n];
        else if (k >= KXP) v = U[(size_t)(k - KXP) * G4H + n];
        g_B[idx] = rtf32(v);
    }
}

// Ax[t][m][j]: j<89 -> x[m][t][j]; j==89 -> 1; else 0 (row stride 128, 96 used)
__global__ void pack_Ax_kernel(const float* __restrict__ x) {
    size_t total = (size_t)TT * BSZ * 128;
    for (size_t idx = (size_t)blockIdx.x * blockDim.x + threadIdx.x; idx < total;
         idx += (size_t)gridDim.x * blockDim.x) {
        int j  = (int)(idx & 127);
        int tm = (int)(idx >> 7);
        int m  = tm & (BSZ - 1);
        int t  = tm >> 11;
        float v = 0.f;
        if (j < FF)       v = x[(size_t)m * (TT * FF) + t * FF + j];
        else if (j == FF) v = 1.f;
        g_Ax[idx] = rtf32(v);
    }
}

// ---------------- persistent LSTM kernel ----------------
// 296 CTAs, each loops over (t, tile) items, t-major, stride NCTAS.
// CTA tile: 128 rows x 128 z-cols (32 h-cols x 4 gates). 8 warps, warp 64x32.
// Cross-step dependency via g_cnt[t][bx] counters (32 producers each).
// Single-sync 3-stage cp.async pipeline; x-part chunks (0-2) precede U chunks
// so chunks 0,1 prefetch BEFORE the dependency wait.
#define STAGE_BYTES 32768
#define SMEM_DYN (3 * STAGE_BYTES)

__global__ __launch_bounds__(256, 2) void lstm_persistent() {
    extern __shared__ char dsm[];
    const uint32_t smem0 = smem_u32(dsm);
    const int tid  = threadIdx.x;
    const int lane = tid & 31;
    const int wid  = tid >> 5;
    const int wm   = wid >> 2;           // 0..1 : 64-row half
    const int wn   = wid & 3;            // 0..3 : 8-h-col group

    // ldmatrix lane addressing
    const int aRowL = wm * 64 + (lane & 15);
    const int aSegL = lane >> 4;
    const int bRowL = wn * 32 + ((lane >> 4) << 3) + (lane & 7);
    const int bSegL = (lane >> 3) & 1;

    const int NITEMS = TT * NTILES;
    for (int it = blockIdx.x; it < NITEMS; it += NCTAS) {
        const int t    = it >> 9;            // / 512
        const int tile = it & (NTILES - 1);
        const int bx   = tile >> 5;          // rowblock 0..15
        const int by   = tile & 31;          // h block 0..31
        const int m0   = bx * 128;
        const int hc0  = by * 32;

        const float* __restrict__ hin  = g_hbuf[t & 1];
        float*       __restrict__ hout = g_hbuf[(t + 1) & 1];

        auto load_chunk = [&](int c, int s) {
            const uint32_t aBase = smem0 + s * STAGE_BYTES;
            const uint32_t bBase = aBase + 16384;
            const int k0 = c * 32;
#pragma unroll
            for (int j = 0; j < 4; j++) {
                int idx = tid + j * 256;
                int row = idx >> 3, seg = idx & 7;
                const float* src;
                if (k0 < KXP)   // x part: W/bias columns (no h dependency)
                    src = g_Ax + ((size_t)t * BSZ + m0 + row) * 128 + k0 + seg * 4;
                else            // U part: needs h from step t-1
                    src = hin + (size_t)(m0 + row) * HH + (k0 - KXP) + seg * 4;
                cp16(aBase + row * 128 + ((seg ^ (row & 7)) << 4), src);
            }
#pragma unroll
            for (int j = 0; j < 4; j++) {
                int idx = tid + j * 256;
                int row = idx >> 3, seg = idx & 7;
                int n = (((row >> 3) & 3) << 10) + hc0 + ((row >> 5) << 3) + (row & 7);
                cp16(bBase + row * 128 + ((seg ^ (row & 7)) << 4),
                     g_B + (size_t)n * KTOT + k0 + seg * 4);
            }
            asm volatile("cp.async.commit_group;" ::: "memory");
        };

        // Prefetch x-part chunks 0,1 before the dependency wait (no h needed).
        load_chunk(0, 0);
        load_chunk(1, 1);

        // Wait for step t-1 rowblock bx to be fully produced (covers h RAW,
        // h ping-pong WAR, and g_c RAW for this tile).
        if (t > 0) {
            if (tid == 0) {
                const int* p = &g_cnt[t - 1][bx];
                int v;
                while (true) {
                    asm volatile("ld.acquire.gpu.global.b32 %0, [%1];"
                                 : "=r"(v) : "l"(p) : "memory");
                    if (v >= NHB) break;
                    __nanosleep(64);
                }
            }
            __syncthreads();
        }

        float acc[4][4][4];   // [mfrag][gate][elem]
#pragma unroll
        for (int mf = 0; mf < 4; mf++)
#pragma unroll
            for (int g = 0; g < 4; g++)
#pragma unroll
                for (int e = 0; e < 4; e++) acc[mf][g][e] = 0.f;

        for (int ch = 0; ch < NCHK; ++ch) {
            // Top of iteration: chunk ch resident after this wait+sync.
            asm volatile("cp.async.wait_group 1;" ::: "memory");
            __syncthreads();

            // Issue load of chunk ch+2 into stage (ch+2)%3 = (ch-1)%3.
            // That stage's reads finished in iteration ch-1, ordered by the
            // sync above -> WAR safe with a single barrier per iteration.
            int cl = ch + 2;
            if (cl < NCHK) load_chunk(cl, cl % 3);
            else asm volatile("cp.async.commit_group;" ::: "memory");

            const uint32_t aBase = smem0 + (ch % 3) * STAGE_BYTES;
            const uint32_t bBase = aBase + 16384;
#pragma unroll
            for (int ks = 0; ks < 4; ++ks) {
                uint32_t b[2][4];
#pragma unroll
                for (int pr = 0; pr < 2; ++pr) {
                    int row = bRowL + pr * 16;
                    int seg = 2 * ks + bSegL;
                    ldm_x4(bBase + row * 128 + ((seg ^ (row & 7)) << 4),
                           b[pr][0], b[pr][1], b[pr][2], b[pr][3]);
                }
#pragma unroll
                for (int mf = 0; mf < 4; ++mf) {
                    int row = aRowL + mf * 16;
                    int seg = 2 * ks + aSegL;
                    uint32_t a0, a1, a2, a3;
                    ldm_x4(aBase + row * 128 + ((seg ^ (row & 7)) << 4),
                           a0, a1, a2, a3);
                    mma_tf32(acc[mf][0][0], acc[mf][0][1], acc[mf][0][2], acc[mf][0][3],
                             a0, a1, a2, a3, b[0][0], b[0][1]);
                    mma_tf32(acc[mf][1][0], acc[mf][1][1], acc[mf][1][2], acc[mf][1][3],
                             a0, a1, a2, a3, b[0][2], b[0][3]);
                    mma_tf32(acc[mf][2][0], acc[mf][2][1], acc[mf][2][2], acc[mf][2][3],
                             a0, a1, a2, a3, b[1][0], b[1][1]);
                    mma_tf32(acc[mf][3][0], acc[mf][3][1], acc[mf][3][2], acc[mf][3][3],
                             a0, a1, a2, a3, b[1][2], b[1][3]);
                }
            }
        }

        // Epilogue: gates + state update in registers.
        {
            const int colg = hc0 + wn * 8 + 2 * (lane & 3);
#pragma unroll
            for (int mf = 0; mf < 4; ++mf) {
                const int r0 = m0 + wm * 64 + mf * 16 + (lane >> 2);
#pragma unroll
                for (int half = 0; half < 2; ++half) {
                    const int r = r0 + half * 8;
                    float2* cp2 = reinterpret_cast<float2*>(&g_c[(size_t)r * HH + colg]);
                    float2* hp2 = reinterpret_cast<float2*>(&hout[(size_t)r * HH + colg]);
                    float2 co = *cp2;
                    float cold[2] = {co.x, co.y};
                    float cn[2], hn[2];
#pragma unroll
                    for (int q = 0; q < 2; ++q) {
                        int e = half * 2 + q;
                        float iv = 1.f / (1.f + __expf(-acc[mf][0][e]));
                        float fv = 1.f / (1.f + __expf(-acc[mf][1][e]));
                        float gv = fmaxf(acc[mf][2][e], 0.f);
                        float ov = 1.f / (1.f + __expf(-acc[mf][3][e]));
                        float c2 = fv * cold[q] + iv * gv;
                        cn[q] = c2;
                        hn[q] = rtf32(ov * fmaxf(c2, 0.f));  // tf32-round for next MMA
                    }
                    *cp2 = make_float2(cn[0], cn[1]);
                    *hp2 = make_float2(hn[0], hn[1]);
                }
            }
        }

        // Publish: this tile's h rows/cols for step t are done.
        __threadfence();
        __syncthreads();
        if (tid == 0) atomicAdd(&g_cnt[t][bx], 1);
    }
}

// ---------------- dense head ----------------
__global__ void dense_kernel(const float* __restrict__ Wd,
                             const float* __restrict__ bd,
                             float* __restrict__ out)
{
    __shared__ float red[8][32];
    const int b = blockIdx.x;
    const int tid = threadIdx.x;
    const int o = tid & 31;
    const int sg = tid >> 5;           // 8 k-segments of 128
    const float* __restrict__ h = &g_hbuf[0][(size_t)b * HH];
    float s = 0.f;
    if (o < OUTN) {
        const int k0 = sg * 128;
#pragma unroll 4
        for (int k = k0; k < k0 + 128; ++k) s += h[k] * Wd[k * OUTN + o];
    }
    red[sg][o] = s;
    __syncthreads();
    if (tid < OUTN) {
        float a = bd[tid];
#pragma unroll
        for (int i = 0; i < 8; ++i) a += red[i][tid];
        out[(size_t)b * OUTN + tid] = a;
    }
}

extern "C" void kernel_launch(void* const* d_in, const int* in_sizes, int n_in,
                              void* d_out, int out_size)
{
    (void)in_sizes; (void)n_in; (void)out_size;
    const float* x  = (const float*)d_in[0];
    const float* W  = (const float*)d_in[1];
    const float* U  = (const float*)d_in[2];
    const float* b  = (const float*)d_in[3];
    const float* Wd = (const float*)d_in[4];
    const float* bd = (const float*)d_in[5];
    float* out = (float*)d_out;

    cudaFuncSetAttribute(lstm_persistent, cudaFuncAttributeMaxDynamicSharedMemorySize,
                         SMEM_DYN);

    zero_state_kernel<<<512, 256>>>();
    pack_B_kernel<<<2048, 256>>>(W, U, b);
    pack_Ax_kernel<<<4096, 256>>>(x);

    lstm_persistent<<<NCTAS, 256, SMEM_DYN>>>();

    dense_kernel<<<BSZ, 256>>>(Wd, bd, out);
}